// round 3
// baseline (speedup 1.0000x reference)
#include <cuda_runtime.h>

// Dilated attention, b=1, n=8192, h=8, d=64, fp32, causal.
// Group 0: heads 0-3, seg 2048, rate 1, offset 0  -> 16 problems, L=2048
// Group 1: heads 4-7, seg 8192, rate 2, offset 1  ->  4 problems, L=4096
// Output: group-1 heads at even positions must be zero.

__global__ void zero_even_kernel(float* __restrict__ out) {
    int idx = blockIdx.x * blockDim.x + threadIdx.x;  // 262144 float4 writes
    if (idx < 4096 * 4 * 16) {
        int f4 = idx & 15;
        int h  = ((idx >> 4) & 3) + 4;
        int a  = idx >> 6;            // 0..4095 -> pos = 2*a (even positions)
        int off = ((2 * a) * 8 + h) * 64 + f4 * 4;
        *reinterpret_cast<float4*>(out + off) = make_float4(0.f, 0.f, 0.f, 0.f);
    }
}

__global__ __launch_bounds__(128, 4) void dilated_attn_kernel(
    const float* __restrict__ Q, const float* __restrict__ K,
    const float* __restrict__ V, float* __restrict__ O)
{
    __shared__ float sQT[64 * 64];  // Q^T  (k-major), prescaled by 1/8
    __shared__ float sKP[64 * 64];  // K^T during S phase; P^T during PV phase
    __shared__ float sV [64 * 64];  // V natural layout

    // ---- decode block -> (problem p, query tile qt), work-descending order ----
    int bx = blockIdx.x;
    int p, qt;
    if (bx < 128) {                       // group-1 tiles qt 63..32 (heaviest)
        qt = 63 - (bx >> 2);
        p  = 16 + (bx & 3);
    } else {                              // qt 31..0: 4 group-1 + 16 group-0 each
        int b2  = bx - 128;
        qt      = 31 - b2 / 20;
        int r20 = b2 % 20;
        p       = (r20 < 4) ? (16 + r20) : (r20 - 4);
    }
    int head, seg_start, rate, offs;
    if (p < 16) { head = p >> 2; seg_start = (p & 3) * 2048; rate = 1; offs = 0; }
    else        { head = p - 12; seg_start = 0;              rate = 2; offs = 1; }

    const int tid = threadIdx.x;
    const int tx  = tid & 7;     // column-group: owns cols {tx*4+j, tx*4+32+j}
    const int ty  = tid >> 3;    // row-group:    owns rows  ty*4+i

    // ---- load Q tile, transposed + prescaled ----
    {
        int r   = tid >> 1;
        int c0  = (tid & 1) * 32;
        int pos = seg_start + offs + (qt * 64 + r) * rate;
        const float4* gq = reinterpret_cast<const float4*>(Q + (pos * 8 + head) * 64 + c0);
        #pragma unroll
        for (int u = 0; u < 8; u++) {
            float4 val = gq[u];
            int kk = c0 + u * 4;
            sQT[(kk + 0) * 64 + r] = val.x * 0.125f;
            sQT[(kk + 1) * 64 + r] = val.y * 0.125f;
            sQT[(kk + 2) * 64 + r] = val.z * 0.125f;
            sQT[(kk + 3) * 64 + r] = val.w * 0.125f;
        }
    }

    float m_i[4], l_i[4], o[4][8];
    #pragma unroll
    for (int i = 0; i < 4; i++) {
        m_i[i] = -1e30f; l_i[i] = 0.f;
        #pragma unroll
        for (int j = 0; j < 8; j++) o[i][j] = 0.f;
    }

    const int ntk = qt + 1;   // causal: key tiles 0..qt
    for (int kt = 0; kt < ntk; kt++) {
        __syncthreads();      // prev PV done reading sKP/sV (and Q store on iter 0)
        // ---- load K (transposed) and V (natural) ----
        {
            int r   = tid >> 1;
            int c0  = (tid & 1) * 32;
            int pos = seg_start + offs + (kt * 64 + r) * rate;
            const float4* gk = reinterpret_cast<const float4*>(K + (pos * 8 + head) * 64 + c0);
            const float4* gv = reinterpret_cast<const float4*>(V + (pos * 8 + head) * 64 + c0);
            #pragma unroll
            for (int u = 0; u < 8; u++) {
                float4 val = gk[u];
                int kk = c0 + u * 4;
                sKP[(kk + 0) * 64 + r] = val.x;
                sKP[(kk + 1) * 64 + r] = val.y;
                sKP[(kk + 2) * 64 + r] = val.z;
                sKP[(kk + 3) * 64 + r] = val.w;
                *reinterpret_cast<float4*>(&sV[r * 64 + c0 + u * 4]) = gv[u];
            }
        }
        __syncthreads();

        // ---- S = Q K^T (prescaled) ----
        float s[4][8];
        #pragma unroll
        for (int i = 0; i < 4; i++)
            #pragma unroll
            for (int j = 0; j < 8; j++) s[i][j] = 0.f;

        #pragma unroll 8
        for (int kk = 0; kk < 64; kk++) {
            float4 qv = *reinterpret_cast<const float4*>(&sQT[kk * 64 + ty * 4]);
            float4 a0 = *reinterpret_cast<const float4*>(&sKP[kk * 64 + tx * 4]);
            float4 a1 = *reinterpret_cast<const float4*>(&sKP[kk * 64 + tx * 4 + 32]);
            float qa[4] = {qv.x, qv.y, qv.z, qv.w};
            float kb[8] = {a0.x, a0.y, a0.z, a0.w, a1.x, a1.y, a1.z, a1.w};
            #pragma unroll
            for (int i = 0; i < 4; i++)
                #pragma unroll
                for (int j = 0; j < 8; j++)
                    s[i][j] = fmaf(qa[i], kb[j], s[i][j]);
        }

        // ---- causal mask (diagonal tile only) ----
        if (kt == qt) {
            #pragma unroll
            for (int i = 0; i < 4; i++) {
                int tq = ty * 4 + i;
                #pragma unroll
                for (int j = 0; j < 8; j++) {
                    int tk = tx * 4 + ((j < 4) ? j : 32 + (j - 4));
                    if (tk > tq) s[i][j] = -1e30f;
                }
            }
        }

        // ---- online softmax (registers only; s becomes P in place) ----
        #pragma unroll
        for (int i = 0; i < 4; i++) {
            float rmax = s[i][0];
            #pragma unroll
            for (int j = 1; j < 8; j++) rmax = fmaxf(rmax, s[i][j]);
            rmax = fmaxf(rmax, __shfl_xor_sync(0xffffffffu, rmax, 1));
            rmax = fmaxf(rmax, __shfl_xor_sync(0xffffffffu, rmax, 2));
            rmax = fmaxf(rmax, __shfl_xor_sync(0xffffffffu, rmax, 4));
            float newm = fmaxf(m_i[i], rmax);
            float corr = __expf(m_i[i] - newm);
            m_i[i] = newm;
            float rs = 0.f;
            #pragma unroll
            for (int j = 0; j < 8; j++) {
                float e = __expf(s[i][j] - newm);
                s[i][j] = e;
                rs += e;
            }
            rs += __shfl_xor_sync(0xffffffffu, rs, 1);
            rs += __shfl_xor_sync(0xffffffffu, rs, 2);
            rs += __shfl_xor_sync(0xffffffffu, rs, 4);
            l_i[i] = l_i[i] * corr + rs;
            #pragma unroll
            for (int j = 0; j < 8; j++) o[i][j] *= corr;
        }

        __syncthreads();   // everyone done reading sKP as K^T
        // ---- store P^T into sKP ----
        #pragma unroll
        for (int i = 0; i < 4; i++)
            #pragma unroll
            for (int j = 0; j < 8; j++) {
                int c = tx * 4 + ((j < 4) ? j : 32 + (j - 4));
                sKP[c * 64 + ty * 4 + i] = s[i][j];
            }
        __syncthreads();

        // ---- O += P V ----
        #pragma unroll 8
        for (int c = 0; c < 64; c++) {
            float4 pv = *reinterpret_cast<const float4*>(&sKP[c * 64 + ty * 4]);
            float4 v0 = *reinterpret_cast<const float4*>(&sV[c * 64 + tx * 4]);
            float4 v1 = *reinterpret_cast<const float4*>(&sV[c * 64 + tx * 4 + 32]);
            float pa[4] = {pv.x, pv.y, pv.z, pv.w};
            float vb[8] = {v0.x, v0.y, v0.z, v0.w, v1.x, v1.y, v1.z, v1.w};
            #pragma unroll
            for (int i = 0; i < 4; i++)
                #pragma unroll
                for (int j = 0; j < 8; j++)
                    o[i][j] = fmaf(pa[i], vb[j], o[i][j]);
        }
    }

    // ---- epilogue: normalize + scatter to global positions ----
    #pragma unroll
    for (int i = 0; i < 4; i++) {
        int tq  = qt * 64 + ty * 4 + i;
        int pos = seg_start + offs + tq * rate;
        float inv = 1.f / l_i[i];
        float* gout = O + (pos * 8 + head) * 64;
        float4 w0 = make_float4(o[i][0] * inv, o[i][1] * inv, o[i][2] * inv, o[i][3] * inv);
        float4 w1 = make_float4(o[i][4] * inv, o[i][5] * inv, o[i][6] * inv, o[i][7] * inv);
        *reinterpret_cast<float4*>(gout + tx * 4)      = w0;
        *reinterpret_cast<float4*>(gout + tx * 4 + 32) = w1;
    }
}

extern "C" void kernel_launch(void* const* d_in, const int* in_sizes, int n_in,
                              void* d_out, int out_size) {
    const float* q = (const float*)d_in[0];
    const float* k = (const float*)d_in[1];
    const float* v = (const float*)d_in[2];
    // d_in[3] = is_causal (always 1 for this dataset)
    float* out = (float*)d_out;

    // Zero the never-written slots (group-1 heads, even positions). Disjoint
    // from attention writes, so no ordering hazard beyond stream order.
    zero_even_kernel<<<1024, 256>>>(out);
    dilated_attn_kernel<<<768, 128>>>(q, k, v, out);
}

// round 4
// speedup vs baseline: 1.6051x; 1.6051x over previous
#include <cuda_runtime.h>
#include <cstdint>

// Dilated attention, b=1, n=8192, h=8, d=64, fp32, causal.
// Group 0: heads 0-3, seg 2048, rate 1, offset 0 -> 16 problems, L=2048
// Group 1: heads 4-7, seg 8192, rate 2, offset 1 ->  4 problems, L=4096
// Tensor-core version: mma.sync.m16n8k8.tf32, 3xTF32 compensation on QK^T.

__global__ void zero_even_kernel(float* __restrict__ out) {
    int idx = blockIdx.x * blockDim.x + threadIdx.x;
    if (idx < 4096 * 4 * 16) {
        int f4 = idx & 15;
        int h  = ((idx >> 4) & 3) + 4;
        int a  = idx >> 6;  // even positions 2*a
        int off = ((2 * a) * 8 + h) * 64 + f4 * 4;
        *reinterpret_cast<float4*>(out + off) = make_float4(0.f, 0.f, 0.f, 0.f);
    }
}

__device__ __forceinline__ float tf32_trunc(float x) {
    return __uint_as_float(__float_as_uint(x) & 0xFFFFE000u);
}
__device__ __forceinline__ uint32_t tf32_rna_bits(float x) {
    uint32_t u;
    asm("cvt.rna.tf32.f32 %0, %1;" : "=r"(u) : "f"(x));
    return u;
}
__device__ __forceinline__ uint32_t fbits(float x) { return __float_as_uint(x); }

// pair layout: within each 8-wide d group, (d, d+4) stored adjacently at (2t, 2t+1)
__device__ __forceinline__ int pidx(int d) {
    return (d & ~7) | (((d & 3) << 1) | ((d >> 2) & 1));
}

__device__ __forceinline__ void mma8(float* c, const uint32_t* a, uint32_t b0, uint32_t b1) {
    asm("mma.sync.aligned.m16n8k8.row.col.f32.tf32.tf32.f32 "
        "{%0,%1,%2,%3}, {%4,%5,%6,%7}, {%8,%9}, {%0,%1,%2,%3};\n"
        : "+f"(c[0]), "+f"(c[1]), "+f"(c[2]), "+f"(c[3])
        : "r"(a[0]), "r"(a[1]), "r"(a[2]), "r"(a[3]), "r"(b0), "r"(b1));
}

#define SQ_STRIDE 68
#define SK_STRIDE 136
#define SV_STRIDE 68
#define SMEM_BYTES ((128 * SQ_STRIDE + 64 * SK_STRIDE + 64 * SV_STRIDE) * 4)

__global__ void __launch_bounds__(128, 2) dilated_attn_mma_kernel(
    const float* __restrict__ Q, const float* __restrict__ K,
    const float* __restrict__ V, float* __restrict__ O)
{
    extern __shared__ float sm[];
    float* sQ = sm;                       // 128 x 68  (fp32, prescaled)
    float* sK = sQ + 128 * SQ_STRIDE;     // 64 x 136  (hi/lo interleaved, d-paired)
    float* sV = sK + 64 * SK_STRIDE;      // 64 x 68   (transposed, key-paired, tf32-rna)

    // ---- decode block -> (problem, qtile), work-descending ----
    int bx = blockIdx.x;
    int head, seg, rate, offs, qt;
    if (bx < 128) {                 // group 1 (L=4096), heaviest first
        qt   = 31 - (bx >> 2);
        head = 4 + (bx & 3);
        seg = 0; rate = 2; offs = 1;
    } else {                        // group 0 (L=2048)
        int b2 = bx - 128;
        qt     = 15 - (b2 >> 4);
        int pp = b2 & 15;
        head = pp >> 2; seg = (pp & 3) * 2048; rate = 1; offs = 0;
    }

    const int tid  = threadIdx.x;
    const int lane = tid & 31;
    const int w    = tid >> 5;
    const int g    = lane >> 2;    // 0..7
    const int tig  = lane & 3;     // 0..3

    // ---- load Q tile (prescaled by 1/8, d pair-reordered) ----
    {
        int row = tid;
        int pos = seg + offs + (qt * 128 + row) * rate;
        const float4* gq = reinterpret_cast<const float4*>(Q + ((size_t)pos * 8 + head) * 64);
        float* qrow = sQ + row * SQ_STRIDE;
        #pragma unroll
        for (int u = 0; u < 16; u++) {
            float4 x = gq[u];
            int d = u * 4;
            qrow[pidx(d + 0)] = x.x * 0.125f;
            qrow[pidx(d + 1)] = x.y * 0.125f;
            qrow[pidx(d + 2)] = x.z * 0.125f;
            qrow[pidx(d + 3)] = x.w * 0.125f;
        }
    }

    float O_[2][8][4];
    float m_[2][2], l_[2][2];
    #pragma unroll
    for (int mt = 0; mt < 2; mt++) {
        m_[mt][0] = -1e30f; m_[mt][1] = -1e30f;
        l_[mt][0] = 0.f;    l_[mt][1] = 0.f;
        #pragma unroll
        for (int nt = 0; nt < 8; nt++)
            #pragma unroll
            for (int j = 0; j < 4; j++) O_[mt][nt][j] = 0.f;
    }

    const int wq  = qt * 128 + 32 * w;   // warp's min query row (local index)
    const int ntk = 2 * qt + 2;          // causal key tiles

    for (int kt = 0; kt < ntk; kt++) {
        __syncthreads();   // previous compute done; also covers Q store on iter 0
        // ---- load K (split hi/lo, interleaved, d-paired) and V (transposed, key-paired, rna) ----
        {
            int key = tid >> 1, dh = tid & 1;
            int pos = seg + offs + (kt * 64 + key) * rate;
            const float4* gk = reinterpret_cast<const float4*>(K + ((size_t)pos * 8 + head) * 64 + dh * 32);
            const float4* gv = reinterpret_cast<const float4*>(V + ((size_t)pos * 8 + head) * 64 + dh * 32);
            float* krow = sK + key * SK_STRIDE;
            int p2k = pidx(key);
            #pragma unroll
            for (int u = 0; u < 8; u++) {
                float4 x = gk[u];
                float4 y = gv[u];
                int d0 = dh * 32 + u * 4;
                float xs[4] = {x.x, x.y, x.z, x.w};
                float ys[4] = {y.x, y.y, y.z, y.w};
                #pragma unroll
                for (int j = 0; j < 4; j++) {
                    int d = d0 + j;
                    float hi = tf32_trunc(xs[j]);
                    int ip = 2 * pidx(d);
                    krow[ip]     = hi;
                    krow[ip + 1] = xs[j] - hi;   // exact residual
                    sV[d * SV_STRIDE + p2k] = __uint_as_float(tf32_rna_bits(ys[j]));
                }
            }
        }
        __syncthreads();

        if (kt * 64 > wq + 31) continue;   // fully-masked warp tile (barriers stay aligned)

        // ---- S = Q K^T via 3xTF32 (q_hi*k_hi + q_lo*k_hi + q_hi*k_lo) ----
        float S_[2][8][4];
        #pragma unroll
        for (int mt = 0; mt < 2; mt++)
            #pragma unroll
            for (int nt = 0; nt < 8; nt++)
                #pragma unroll
                for (int j = 0; j < 4; j++) S_[mt][nt][j] = 0.f;

        #pragma unroll
        for (int dk = 0; dk < 8; dk++) {
            uint32_t ah[2][4], al[2][4];
            #pragma unroll
            for (int mt = 0; mt < 2; mt++) {
                int row = 32 * w + 16 * mt + g;
                float2 q0 = *reinterpret_cast<const float2*>(&sQ[row * SQ_STRIDE + dk * 8 + 2 * tig]);
                float2 q1 = *reinterpret_cast<const float2*>(&sQ[(row + 8) * SQ_STRIDE + dk * 8 + 2 * tig]);
                float h;
                h = tf32_trunc(q0.x); ah[mt][0] = fbits(h); al[mt][0] = fbits(q0.x - h);
                h = tf32_trunc(q1.x); ah[mt][1] = fbits(h); al[mt][1] = fbits(q1.x - h);
                h = tf32_trunc(q0.y); ah[mt][2] = fbits(h); al[mt][2] = fbits(q0.y - h);
                h = tf32_trunc(q1.y); ah[mt][3] = fbits(h); al[mt][3] = fbits(q1.y - h);
            }
            #pragma unroll
            for (int nt = 0; nt < 8; nt++) {
                float4 kk = *reinterpret_cast<const float4*>(&sK[(8 * nt + g) * SK_STRIDE + dk * 16 + 4 * tig]);
                uint32_t bh0 = fbits(kk.x), bl0 = fbits(kk.y);
                uint32_t bh1 = fbits(kk.z), bl1 = fbits(kk.w);
                mma8(S_[0][nt], ah[0], bh0, bh1);
                mma8(S_[1][nt], ah[1], bh0, bh1);
                mma8(S_[0][nt], al[0], bh0, bh1);
                mma8(S_[1][nt], al[1], bh0, bh1);
                mma8(S_[0][nt], ah[0], bl0, bl1);
                mma8(S_[1][nt], ah[1], bl0, bl1);
            }
        }

        // ---- causal mask (partial tiles only) ----
        if (kt * 64 + 63 > wq) {
            #pragma unroll
            for (int mt = 0; mt < 2; mt++)
                #pragma unroll
                for (int nt = 0; nt < 8; nt++)
                    #pragma unroll
                    for (int j = 0; j < 4; j++) {
                        int tq = wq + 16 * mt + g + ((j >= 2) ? 8 : 0);
                        int tk = kt * 64 + nt * 8 + 2 * tig + (j & 1);
                        if (tk > tq) S_[mt][nt][j] = -1e30f;
                    }
        }

        // ---- online softmax (P truncated to tf32; l summed over truncated P) ----
        #pragma unroll
        for (int mt = 0; mt < 2; mt++)
            #pragma unroll
            for (int rh = 0; rh < 2; rh++) {
                int j0 = rh * 2;
                float rmax = -1e30f;
                #pragma unroll
                for (int nt = 0; nt < 8; nt++) {
                    rmax = fmaxf(rmax, S_[mt][nt][j0]);
                    rmax = fmaxf(rmax, S_[mt][nt][j0 + 1]);
                }
                rmax = fmaxf(rmax, __shfl_xor_sync(0xffffffffu, rmax, 1));
                rmax = fmaxf(rmax, __shfl_xor_sync(0xffffffffu, rmax, 2));
                float newm = fmaxf(m_[mt][rh], rmax);
                float corr = __expf(m_[mt][rh] - newm);
                m_[mt][rh] = newm;
                float rs = 0.f;
                #pragma unroll
                for (int nt = 0; nt < 8; nt++) {
                    float e0 = tf32_trunc(__expf(S_[mt][nt][j0]     - newm));
                    float e1 = tf32_trunc(__expf(S_[mt][nt][j0 + 1] - newm));
                    S_[mt][nt][j0]     = e0;
                    S_[mt][nt][j0 + 1] = e1;
                    rs += e0 + e1;
                }
                rs += __shfl_xor_sync(0xffffffffu, rs, 1);
                rs += __shfl_xor_sync(0xffffffffu, rs, 2);
                l_[mt][rh] = l_[mt][rh] * corr + rs;
                #pragma unroll
                for (int nt = 0; nt < 8; nt++) {
                    O_[mt][nt][j0]     *= corr;
                    O_[mt][nt][j0 + 1] *= corr;
                }
            }

        // ---- O += P V  (P: C-layout -> A-layout via quad shuffles) ----
        const int srcA = (lane & ~3) | (tig >> 1);
        const int srcB = srcA + 2;
        const bool odd = (tig & 1);
        #pragma unroll
        for (int kk2 = 0; kk2 < 8; kk2++) {
            uint32_t pa[2][4];
            #pragma unroll
            for (int mt = 0; mt < 2; mt++) {
                float x0 = __shfl_sync(0xffffffffu, S_[mt][kk2][0], srcA);
                float x1 = __shfl_sync(0xffffffffu, S_[mt][kk2][1], srcA);
                float x2 = __shfl_sync(0xffffffffu, S_[mt][kk2][2], srcA);
                float x3 = __shfl_sync(0xffffffffu, S_[mt][kk2][3], srcA);
                float y0 = __shfl_sync(0xffffffffu, S_[mt][kk2][0], srcB);
                float y1 = __shfl_sync(0xffffffffu, S_[mt][kk2][1], srcB);
                float y2 = __shfl_sync(0xffffffffu, S_[mt][kk2][2], srcB);
                float y3 = __shfl_sync(0xffffffffu, S_[mt][kk2][3], srcB);
                pa[mt][0] = fbits(odd ? x1 : x0);
                pa[mt][1] = fbits(odd ? x3 : x2);
                pa[mt][2] = fbits(odd ? y1 : y0);
                pa[mt][3] = fbits(odd ? y3 : y2);
            }
            #pragma unroll
            for (int nt = 0; nt < 8; nt++) {
                float2 vv = *reinterpret_cast<const float2*>(&sV[(8 * nt + g) * SV_STRIDE + kk2 * 8 + 2 * tig]);
                uint32_t vb0 = fbits(vv.x), vb1 = fbits(vv.y);
                mma8(O_[0][nt], pa[0], vb0, vb1);
                mma8(O_[1][nt], pa[1], vb0, vb1);
            }
        }
    }

    // ---- epilogue ----
    #pragma unroll
    for (int mt = 0; mt < 2; mt++)
        #pragma unroll
        for (int rh = 0; rh < 2; rh++) {
            float inv = 1.f / l_[mt][rh];
            int tq  = qt * 128 + 32 * w + 16 * mt + g + rh * 8;
            int pos = seg + offs + tq * rate;
            float* go = O + ((size_t)pos * 8 + head) * 64;
            int j0 = rh * 2;
            #pragma unroll
            for (int nt = 0; nt < 8; nt++) {
                float2 wv = make_float2(O_[mt][nt][j0] * inv, O_[mt][nt][j0 + 1] * inv);
                *reinterpret_cast<float2*>(&go[nt * 8 + 2 * tig]) = wv;
            }
        }
}

extern "C" void kernel_launch(void* const* d_in, const int* in_sizes, int n_in,
                              void* d_out, int out_size) {
    const float* q = (const float*)d_in[0];
    const float* k = (const float*)d_in[1];
    const float* v = (const float*)d_in[2];
    float* out = (float*)d_out;

    static bool attr_set = false;
    if (!attr_set) {
        cudaFuncSetAttribute(dilated_attn_mma_kernel,
                             cudaFuncAttributeMaxDynamicSharedMemorySize, SMEM_BYTES);
        attr_set = true;
    }

    zero_even_kernel<<<1024, 256>>>(out);
    dilated_attn_mma_kernel<<<384, 128, SMEM_BYTES>>>(q, k, v, out);
}

// round 8
// speedup vs baseline: 2.1347x; 1.3300x over previous
#include <cuda_runtime.h>
#include <cstdint>

// Dilated attention, b=1, n=8192, h=8, d=64, fp32, causal.
// Group 0: heads 0-3, seg 2048, rate 1, offset 0 -> 16 problems, L=2048
// Group 1: heads 4-7, seg 8192, rate 2, offset 1 ->  4 problems, L=4096
// Tensor cores: mma.sync.m16n8k8.tf32.
// QK^T: Q split (rna-hi + lo), K rna-rounded -> 2 MMAs, |S| err ~6e-5.
// PV:   P tf32-truncated with consistent l; V rna-rounded.

__global__ void zero_even_kernel(float* __restrict__ out) {
    int idx = blockIdx.x * blockDim.x + threadIdx.x;
    if (idx < 4096 * 4 * 16) {
        int f4 = idx & 15;
        int h  = ((idx >> 4) & 3) + 4;
        int a  = idx >> 6;  // even positions 2*a
        int off = ((2 * a) * 8 + h) * 64 + f4 * 4;
        *reinterpret_cast<float4*>(out + off) = make_float4(0.f, 0.f, 0.f, 0.f);
    }
}

__device__ __forceinline__ float tf32_trunc(float x) {
    return __uint_as_float(__float_as_uint(x) & 0xFFFFE000u);
}
__device__ __forceinline__ float tf32_rna(float x) {
    uint32_t u;
    asm("cvt.rna.tf32.f32 %0, %1;" : "=r"(u) : "f"(x));
    return __uint_as_float(u);
}
__device__ __forceinline__ uint32_t fbits(float x) { return __float_as_uint(x); }

// pair layout: within each 8-wide group, (t, t+4) stored adjacently at (2t, 2t+1)
__device__ __forceinline__ int pidx(int d) {
    return (d & ~7) | (((d & 3) << 1) | ((d >> 2) & 1));
}

__device__ __forceinline__ void mma8(float* c, const uint32_t* a, uint32_t b0, uint32_t b1) {
    asm("mma.sync.aligned.m16n8k8.row.col.f32.tf32.tf32.f32 "
        "{%0,%1,%2,%3}, {%4,%5,%6,%7}, {%8,%9}, {%0,%1,%2,%3};\n"
        : "+f"(c[0]), "+f"(c[1]), "+f"(c[2]), "+f"(c[3])
        : "r"(a[0]), "r"(a[1]), "r"(a[2]), "r"(a[3]), "r"(b0), "r"(b1));
}

#define SQ_STRIDE 68
#define SK_STRIDE 68
#define SV_STRIDE 68
#define SMEM_BYTES ((128 * SQ_STRIDE + 64 * SK_STRIDE + 64 * SV_STRIDE) * 4)

__global__ void __launch_bounds__(256, 2) dilated_attn_mma_kernel(
    const float* __restrict__ Q, const float* __restrict__ K,
    const float* __restrict__ V, float* __restrict__ O)
{
    extern __shared__ float sm[];
    float* sQ = sm;                       // 128 x 68  fp32 (prescaled 1/8), d pair-ordered
    float* sK = sQ + 128 * SQ_STRIDE;     // 64 x 68   tf32-rna, d pair-ordered
    float* sV = sK + 64 * SK_STRIDE;      // 64 x 68   transposed, key pair-ordered, tf32-rna

    // ---- decode block -> (problem, qtile of 128 rows), work-descending ----
    int bx = blockIdx.x;
    int head, seg, rate, offs, qt;
    if (bx < 128) {                 // group 1 (L=4096, 32 qtiles), heaviest first
        qt   = 31 - (bx >> 2);
        head = 4 + (bx & 3);
        seg = 0; rate = 2; offs = 1;
    } else {                        // group 0 (L=2048, 16 qtiles)
        int b2 = bx - 128;
        qt     = 15 - (b2 >> 4);
        int pp = b2 & 15;
        head = pp >> 2; seg = (pp & 3) * 2048; rate = 1; offs = 0;
    }

    const int tid  = threadIdx.x;
    const int lane = tid & 31;
    const int w    = tid >> 5;     // 8 warps, warp owns rows 16w..16w+15
    const int g    = lane >> 2;    // 0..7
    const int tig  = lane & 3;     // 0..3

    // ---- load Q tile (prescaled by 1/8, d pair-reordered) ----
    {
        int row = tid >> 1, dh = tid & 1;
        int pos = seg + offs + (qt * 128 + row) * rate;
        const float4* gq = reinterpret_cast<const float4*>(Q + ((size_t)pos * 8 + head) * 64 + dh * 32);
        float* qrow = sQ + row * SQ_STRIDE;
        #pragma unroll
        for (int u = 0; u < 8; u++) {
            float4 x = gq[u];
            int d = dh * 32 + u * 4;
            qrow[pidx(d + 0)] = x.x * 0.125f;
            qrow[pidx(d + 1)] = x.y * 0.125f;
            qrow[pidx(d + 2)] = x.z * 0.125f;
            qrow[pidx(d + 3)] = x.w * 0.125f;
        }
    }

    float O_[8][4];
    float m_[2], l_[2];
    m_[0] = -1e30f; m_[1] = -1e30f; l_[0] = 0.f; l_[1] = 0.f;
    #pragma unroll
    for (int nt = 0; nt < 8; nt++)
        #pragma unroll
        for (int j = 0; j < 4; j++) O_[nt][j] = 0.f;

    const int wq  = qt * 128 + 16 * w;   // warp's min query row (local index)
    const int ntk = 2 * qt + 2;          // causal key tiles of 64

    for (int kt = 0; kt < ntk; kt++) {
        __syncthreads();   // previous compute done (covers Q store on iter 0)
        // ---- load K (rna, d pair-ordered) and V (transposed, key pair-ordered, rna) ----
        {
            int key = tid >> 2, dq = tid & 3;
            int pos = seg + offs + (kt * 64 + key) * rate;
            const float4* gk = reinterpret_cast<const float4*>(K + ((size_t)pos * 8 + head) * 64 + dq * 16);
            const float4* gv = reinterpret_cast<const float4*>(V + ((size_t)pos * 8 + head) * 64 + dq * 16);
            float* krow = sK + key * SK_STRIDE;
            int p2k = pidx(key);
            #pragma unroll
            for (int u = 0; u < 4; u++) {
                float4 x = gk[u];
                float4 y = gv[u];
                int d0 = dq * 16 + u * 4;
                float xs[4] = {x.x, x.y, x.z, x.w};
                float ys[4] = {y.x, y.y, y.z, y.w};
                #pragma unroll
                for (int j = 0; j < 4; j++) {
                    int d = d0 + j;
                    krow[pidx(d)] = tf32_rna(xs[j]);
                    sV[d * SV_STRIDE + p2k] = tf32_rna(ys[j]);
                }
            }
        }
        __syncthreads();

        if (kt * 64 > wq + 15) continue;   // fully-masked warp tile

        // ---- S = Q K^T via 2xTF32 (q_hi*k + q_lo*k), k rna-rounded ----
        float S_[8][4];
        #pragma unroll
        for (int nt = 0; nt < 8; nt++)
            #pragma unroll
            for (int j = 0; j < 4; j++) S_[nt][j] = 0.f;

        #pragma unroll
        for (int dk = 0; dk < 8; dk++) {
            uint32_t ah[4], al[4];
            {
                int row = 16 * w + g;
                float2 q0 = *reinterpret_cast<const float2*>(&sQ[row * SQ_STRIDE + dk * 8 + 2 * tig]);
                float2 q1 = *reinterpret_cast<const float2*>(&sQ[(row + 8) * SQ_STRIDE + dk * 8 + 2 * tig]);
                float h;
                h = tf32_rna(q0.x); ah[0] = fbits(h); al[0] = fbits(q0.x - h);
                h = tf32_rna(q1.x); ah[1] = fbits(h); al[1] = fbits(q1.x - h);
                h = tf32_rna(q0.y); ah[2] = fbits(h); al[2] = fbits(q0.y - h);
                h = tf32_rna(q1.y); ah[3] = fbits(h); al[3] = fbits(q1.y - h);
            }
            #pragma unroll
            for (int nt = 0; nt < 8; nt++) {
                float2 kk = *reinterpret_cast<const float2*>(&sK[(8 * nt + g) * SK_STRIDE + dk * 8 + 2 * tig]);
                uint32_t b0 = fbits(kk.x), b1 = fbits(kk.y);
                mma8(S_[nt], ah, b0, b1);
                mma8(S_[nt], al, b0, b1);
            }
        }

        // ---- causal mask (partial tiles only) ----
        if (kt * 64 + 63 > wq) {
            #pragma unroll
            for (int nt = 0; nt < 8; nt++)
                #pragma unroll
                for (int j = 0; j < 4; j++) {
                    int tq = wq + g + ((j >= 2) ? 8 : 0);
                    int tk = kt * 64 + nt * 8 + 2 * tig + (j & 1);
                    if (tk > tq) S_[nt][j] = -1e30f;
                }
        }

        // ---- online softmax (P tf32-truncated; l summed over truncated P) ----
        #pragma unroll
        for (int rh = 0; rh < 2; rh++) {
            int j0 = rh * 2;
            float rmax = -1e30f;
            #pragma unroll
            for (int nt = 0; nt < 8; nt++) {
                rmax = fmaxf(rmax, S_[nt][j0]);
                rmax = fmaxf(rmax, S_[nt][j0 + 1]);
            }
            rmax = fmaxf(rmax, __shfl_xor_sync(0xffffffffu, rmax, 1));
            rmax = fmaxf(rmax, __shfl_xor_sync(0xffffffffu, rmax, 2));
            float newm = fmaxf(m_[rh], rmax);
            float corr = __expf(m_[rh] - newm);
            m_[rh] = newm;
            float rs = 0.f;
            #pragma unroll
            for (int nt = 0; nt < 8; nt++) {
                float e0 = tf32_trunc(__expf(S_[nt][j0]     - newm));
                float e1 = tf32_trunc(__expf(S_[nt][j0 + 1] - newm));
                S_[nt][j0]     = e0;
                S_[nt][j0 + 1] = e1;
                rs += e0 + e1;
            }
            rs += __shfl_xor_sync(0xffffffffu, rs, 1);
            rs += __shfl_xor_sync(0xffffffffu, rs, 2);
            l_[rh] = l_[rh] * corr + rs;
            #pragma unroll
            for (int nt = 0; nt < 8; nt++) {
                O_[nt][j0]     *= corr;
                O_[nt][j0 + 1] *= corr;
            }
        }

        // ---- O += P V  (P: C-layout -> A-layout via quad shuffles) ----
        const int srcA = (lane & ~3) | (tig >> 1);
        const int srcB = srcA + 2;
        const bool odd = (tig & 1);
        #pragma unroll
        for (int kk2 = 0; kk2 < 8; kk2++) {
            uint32_t pa[4];
            {
                float x0 = __shfl_sync(0xffffffffu, S_[kk2][0], srcA);
                float x1 = __shfl_sync(0xffffffffu, S_[kk2][1], srcA);
                float x2 = __shfl_sync(0xffffffffu, S_[kk2][2], srcA);
                float x3 = __shfl_sync(0xffffffffu, S_[kk2][3], srcA);
                float y0 = __shfl_sync(0xffffffffu, S_[kk2][0], srcB);
                float y1 = __shfl_sync(0xffffffffu, S_[kk2][1], srcB);
                float y2 = __shfl_sync(0xffffffffu, S_[kk2][2], srcB);
                float y3 = __shfl_sync(0xffffffffu, S_[kk2][3], srcB);
                pa[0] = fbits(odd ? x1 : x0);
                pa[1] = fbits(odd ? x3 : x2);
                pa[2] = fbits(odd ? y1 : y0);
                pa[3] = fbits(odd ? y3 : y2);
            }
            #pragma unroll
            for (int nt = 0; nt < 8; nt++) {
                float2 vv = *reinterpret_cast<const float2*>(&sV[(8 * nt + g) * SV_STRIDE + kk2 * 8 + 2 * tig]);
                mma8(O_[nt], pa, fbits(vv.x), fbits(vv.y));
            }
        }
    }

    // ---- epilogue ----
    #pragma unroll
    for (int rh = 0; rh < 2; rh++) {
        float inv = 1.f / l_[rh];
        int tq  = qt * 128 + 16 * w + g + rh * 8;
        int pos = seg + offs + tq * rate;
        float* go = O + ((size_t)pos * 8 + head) * 64;
        int j0 = rh * 2;
        #pragma unroll
        for (int nt = 0; nt < 8; nt++) {
            float2 wv = make_float2(O_[nt][j0] * inv, O_[nt][j0 + 1] * inv);
            *reinterpret_cast<float2*>(&go[nt * 8 + 2 * tig]) = wv;
        }
    }
}

extern "C" void kernel_launch(void* const* d_in, const int* in_sizes, int n_in,
                              void* d_out, int out_size) {
    const float* q = (const float*)d_in[0];
    const float* k = (const float*)d_in[1];
    const float* v = (const float*)d_in[2];
    float* out = (float*)d_out;

    static bool attr_set = false;
    if (!attr_set) {
        cudaFuncSetAttribute(dilated_attn_mma_kernel,
                             cudaFuncAttributeMaxDynamicSharedMemorySize, SMEM_BYTES);
        attr_set = true;
    }

    zero_even_kernel<<<1024, 256>>>(out);
    dilated_attn_mma_kernel<<<384, 256, SMEM_BYTES>>>(q, k, v, out);
}

// round 9
// speedup vs baseline: 2.7258x; 1.2769x over previous
#include <cuda_runtime.h>
#include <cstdint>

// Dilated attention, b=1, n=8192, h=8, d=64, fp32, causal.
// Group 0: heads 0-3, seg 2048, rate 1, offset 0 -> 16 problems, L=2048
// Group 1: heads 4-7, seg 8192, rate 2, offset 1 ->  4 problems, L=4096
// mma.sync.m16n8k8.tf32; QK^T 2xTF32 (Q split, K rna); PV with rna-V and
// truncated-P-consistent normalization.
// R8: double-buffered K/V (1 barrier/tile), permute-in-register STS.128,
// stride-72 split-half smem layout (conflict-free LDS/STS).

__global__ void zero_even_kernel(float* __restrict__ out) {
    int idx = blockIdx.x * blockDim.x + threadIdx.x;
    if (idx < 4096 * 4 * 16) {
        int f4 = idx & 15;
        int h  = ((idx >> 4) & 3) + 4;
        int a  = idx >> 6;  // even positions 2*a
        int off = ((2 * a) * 8 + h) * 64 + f4 * 4;
        *reinterpret_cast<float4*>(out + off) = make_float4(0.f, 0.f, 0.f, 0.f);
    }
}

__device__ __forceinline__ float tf32_trunc(float x) {
    return __uint_as_float(__float_as_uint(x) & 0xFFFFE000u);
}
__device__ __forceinline__ float tf32_rna(float x) {
    uint32_t u;
    asm("cvt.rna.tf32.f32 %0, %1;" : "=r"(u) : "f"(x));
    return __uint_as_float(u);
}
__device__ __forceinline__ uint32_t fbits(float x) { return __float_as_uint(x); }

// row geometry: 72-float stride; d-groups 0..3 at 8g, groups 4..7 at 36+8(g-4)
__device__ __forceinline__ constexpr int GOFF(int g) {
    return (g < 4) ? 8 * g : 36 + 8 * (g - 4);
}
// V natural d with halves at 0 / +36
__device__ __forceinline__ constexpr int VOFF(int d) {
    return (d < 32) ? d : d + 4;
}

__device__ __forceinline__ void mma8(float* c, const uint32_t* a, uint32_t b0, uint32_t b1) {
    asm("mma.sync.aligned.m16n8k8.row.col.f32.tf32.tf32.f32 "
        "{%0,%1,%2,%3}, {%4,%5,%6,%7}, {%8,%9}, {%0,%1,%2,%3};\n"
        : "+f"(c[0]), "+f"(c[1]), "+f"(c[2]), "+f"(c[3])
        : "r"(a[0]), "r"(a[1]), "r"(a[2]), "r"(a[3]), "r"(b0), "r"(b1));
}

#define RS 72
#define SMEM_FLOATS (128 * RS + 4 * 64 * RS)
#define SMEM_BYTES  (SMEM_FLOATS * 4)

__global__ void __launch_bounds__(256, 2) dilated_attn_mma_kernel(
    const float* __restrict__ Q, const float* __restrict__ K,
    const float* __restrict__ V, float* __restrict__ O)
{
    extern __shared__ float sm[];
    float* sQ  = sm;                    // 128 x 72, pair-ordered groups, prescaled 1/8
    float* sK0 = sQ  + 128 * RS;        // 64 x 72, key rows, pair-ordered d, rna
    float* sK1 = sK0 + 64 * RS;
    float* sV0 = sK1 + 64 * RS;         // 64 x 72, key rows, natural d (split), rna
    float* sV1 = sV0 + 64 * RS;

    // ---- decode block -> (problem, qtile of 128 rows), work-descending ----
    int bx = blockIdx.x;
    int head, seg, rate, offs, qt;
    if (bx < 128) {                 // group 1 (L=4096, 32 qtiles), heaviest first
        qt   = 31 - (bx >> 2);
        head = 4 + (bx & 3);
        seg = 0; rate = 2; offs = 1;
    } else {                        // group 0 (L=2048, 16 qtiles)
        int b2 = bx - 128;
        qt     = 15 - (b2 >> 4);
        int pp = b2 & 15;
        head = pp >> 2; seg = (pp & 3) * 2048; rate = 1; offs = 0;
    }

    const int tid  = threadIdx.x;
    const int lane = tid & 31;
    const int w    = tid >> 5;     // 8 warps; warp owns query rows 16w..16w+15
    const int g    = lane >> 2;    // 0..7
    const int tig  = lane & 3;     // 0..3

    // per-thread K/V load mapping
    const int key = tid >> 2, dq = tid & 3;
    const float* gkbase = K + (size_t)head * 64 + dq * 16;
    const float* gvbase = V + (size_t)head * 64 + dq * 16;

    // ---- prologue: load Q tile (prescale 1/8, group-permuted, STS.128) ----
    {
        int row = tid >> 1, dh = tid & 1;
        int pos = seg + offs + (qt * 128 + row) * rate;
        const float4* gq = reinterpret_cast<const float4*>(Q + ((size_t)pos * 8 + head) * 64 + dh * 32);
        float* qrow = sQ + row * RS;
        #pragma unroll
        for (int grp = 0; grp < 4; grp++) {
            float4 x = gq[2 * grp];
            float4 y = gq[2 * grp + 1];
            x.x *= 0.125f; x.y *= 0.125f; x.z *= 0.125f; x.w *= 0.125f;
            y.x *= 0.125f; y.y *= 0.125f; y.z *= 0.125f; y.w *= 0.125f;
            int go = GOFF(4 * dh + grp);
            // pair-permute [a0..a7] -> [a0,a4,a1,a5 | a2,a6,a3,a7]
            *reinterpret_cast<float4*>(qrow + go)     = make_float4(x.x, y.x, x.y, y.y);
            *reinterpret_cast<float4*>(qrow + go + 4) = make_float4(x.z, y.z, x.w, y.w);
        }
    }
    // ---- prologue: load key tile 0 into buffer 0 ----
    {
        int pos = seg + offs + key * rate;
        const float4* gk = reinterpret_cast<const float4*>(gkbase + (size_t)pos * 512);
        const float4* gv = reinterpret_cast<const float4*>(gvbase + (size_t)pos * 512);
        float4 kx[4], vx[4];
        #pragma unroll
        for (int u = 0; u < 4; u++) { kx[u] = gk[u]; vx[u] = gv[u]; }
        float* krow = sK0 + key * RS;
        float* vrow = sV0 + key * RS;
        #pragma unroll
        for (int u = 0; u < 4; u++) {
            kx[u].x = tf32_rna(kx[u].x); kx[u].y = tf32_rna(kx[u].y);
            kx[u].z = tf32_rna(kx[u].z); kx[u].w = tf32_rna(kx[u].w);
            vx[u].x = tf32_rna(vx[u].x); vx[u].y = tf32_rna(vx[u].y);
            vx[u].z = tf32_rna(vx[u].z); vx[u].w = tf32_rna(vx[u].w);
        }
        int g0 = GOFF(2 * dq), g1 = GOFF(2 * dq + 1);
        *reinterpret_cast<float4*>(krow + g0)     = make_float4(kx[0].x, kx[1].x, kx[0].y, kx[1].y);
        *reinterpret_cast<float4*>(krow + g0 + 4) = make_float4(kx[0].z, kx[1].z, kx[0].w, kx[1].w);
        *reinterpret_cast<float4*>(krow + g1)     = make_float4(kx[2].x, kx[3].x, kx[2].y, kx[3].y);
        *reinterpret_cast<float4*>(krow + g1 + 4) = make_float4(kx[2].z, kx[3].z, kx[2].w, kx[3].w);
        int vo = (dq < 2) ? dq * 16 : 36 + (dq - 2) * 16;
        #pragma unroll
        for (int u = 0; u < 4; u++)
            *reinterpret_cast<float4*>(vrow + vo + 4 * u) = vx[u];
    }

    float O_[8][4];
    float m_[2], l_[2];
    m_[0] = -1e30f; m_[1] = -1e30f; l_[0] = 0.f; l_[1] = 0.f;
    #pragma unroll
    for (int nt = 0; nt < 8; nt++)
        #pragma unroll
        for (int j = 0; j < 4; j++) O_[nt][j] = 0.f;

    const int wq  = qt * 128 + 16 * w;   // warp's min query row (problem-local)
    const int ntk = 2 * qt + 2;          // causal key tiles of 64

    __syncthreads();

    for (int kt = 0; kt < ntk; kt++) {
        float* sK = (kt & 1) ? sK1 : sK0;
        float* sV = (kt & 1) ? sV1 : sV0;

        // ---- prefetch next key tile into the other buffer ----
        if (kt + 1 < ntk) {
            int pos = seg + offs + ((kt + 1) * 64 + key) * rate;
            const float4* gk = reinterpret_cast<const float4*>(gkbase + (size_t)pos * 512);
            const float4* gv = reinterpret_cast<const float4*>(gvbase + (size_t)pos * 512);
            float4 kx[4], vx[4];
            #pragma unroll
            for (int u = 0; u < 4; u++) { kx[u] = gk[u]; vx[u] = gv[u]; }
            float* krow = ((kt & 1) ? sK0 : sK1) + key * RS;
            float* vrow = ((kt & 1) ? sV0 : sV1) + key * RS;
            #pragma unroll
            for (int u = 0; u < 4; u++) {
                kx[u].x = tf32_rna(kx[u].x); kx[u].y = tf32_rna(kx[u].y);
                kx[u].z = tf32_rna(kx[u].z); kx[u].w = tf32_rna(kx[u].w);
                vx[u].x = tf32_rna(vx[u].x); vx[u].y = tf32_rna(vx[u].y);
                vx[u].z = tf32_rna(vx[u].z); vx[u].w = tf32_rna(vx[u].w);
            }
            int g0 = GOFF(2 * dq), g1 = GOFF(2 * dq + 1);
            *reinterpret_cast<float4*>(krow + g0)     = make_float4(kx[0].x, kx[1].x, kx[0].y, kx[1].y);
            *reinterpret_cast<float4*>(krow + g0 + 4) = make_float4(kx[0].z, kx[1].z, kx[0].w, kx[1].w);
            *reinterpret_cast<float4*>(krow + g1)     = make_float4(kx[2].x, kx[3].x, kx[2].y, kx[3].y);
            *reinterpret_cast<float4*>(krow + g1 + 4) = make_float4(kx[2].z, kx[3].z, kx[2].w, kx[3].w);
            int vo = (dq < 2) ? dq * 16 : 36 + (dq - 2) * 16;
            #pragma unroll
            for (int u = 0; u < 4; u++)
                *reinterpret_cast<float4*>(vrow + vo + 4 * u) = vx[u];
        }

        if (kt * 64 <= wq + 15) {   // warp has unmasked work in this key tile
            // ---- S = Q K^T via 2xTF32 ----
            float S_[8][4];
            #pragma unroll
            for (int nt = 0; nt < 8; nt++)
                #pragma unroll
                for (int j = 0; j < 4; j++) S_[nt][j] = 0.f;

            #pragma unroll
            for (int dk = 0; dk < 8; dk++) {
                int qo = GOFF(dk);
                uint32_t ah[4], al[4];
                {
                    int row = 16 * w + g;
                    float2 q0 = *reinterpret_cast<const float2*>(&sQ[row * RS + qo + 2 * tig]);
                    float2 q1 = *reinterpret_cast<const float2*>(&sQ[(row + 8) * RS + qo + 2 * tig]);
                    float h;
                    h = tf32_rna(q0.x); ah[0] = fbits(h); al[0] = fbits(q0.x - h);
                    h = tf32_rna(q1.x); ah[1] = fbits(h); al[1] = fbits(q1.x - h);
                    h = tf32_rna(q0.y); ah[2] = fbits(h); al[2] = fbits(q0.y - h);
                    h = tf32_rna(q1.y); ah[3] = fbits(h); al[3] = fbits(q1.y - h);
                }
                #pragma unroll
                for (int nt = 0; nt < 8; nt++) {
                    float2 kk = *reinterpret_cast<const float2*>(&sK[(8 * nt + g) * RS + qo + 2 * tig]);
                    uint32_t b0 = fbits(kk.x), b1 = fbits(kk.y);
                    mma8(S_[nt], ah, b0, b1);
                    mma8(S_[nt], al, b0, b1);
                }
            }

            // ---- causal mask (partial tiles only) ----
            if (kt * 64 + 63 > wq) {
                #pragma unroll
                for (int nt = 0; nt < 8; nt++)
                    #pragma unroll
                    for (int j = 0; j < 4; j++) {
                        int tq = wq + g + ((j >= 2) ? 8 : 0);
                        int tk = kt * 64 + nt * 8 + 2 * tig + (j & 1);
                        if (tk > tq) S_[nt][j] = -1e30f;
                    }
            }

            // ---- online softmax (P tf32-truncated; l over truncated P) ----
            #pragma unroll
            for (int rh = 0; rh < 2; rh++) {
                int j0 = rh * 2;
                float rmax = -1e30f;
                #pragma unroll
                for (int nt = 0; nt < 8; nt++) {
                    rmax = fmaxf(rmax, S_[nt][j0]);
                    rmax = fmaxf(rmax, S_[nt][j0 + 1]);
                }
                rmax = fmaxf(rmax, __shfl_xor_sync(0xffffffffu, rmax, 1));
                rmax = fmaxf(rmax, __shfl_xor_sync(0xffffffffu, rmax, 2));
                float newm = fmaxf(m_[rh], rmax);
                float corr = __expf(m_[rh] - newm);
                m_[rh] = newm;
                float rs = 0.f;
                #pragma unroll
                for (int nt = 0; nt < 8; nt++) {
                    float e0 = tf32_trunc(__expf(S_[nt][j0]     - newm));
                    float e1 = tf32_trunc(__expf(S_[nt][j0 + 1] - newm));
                    S_[nt][j0]     = e0;
                    S_[nt][j0 + 1] = e1;
                    rs += e0 + e1;
                }
                rs += __shfl_xor_sync(0xffffffffu, rs, 1);
                rs += __shfl_xor_sync(0xffffffffu, rs, 2);
                l_[rh] = l_[rh] * corr + rs;
                #pragma unroll
                for (int nt = 0; nt < 8; nt++) {
                    O_[nt][j0]     *= corr;
                    O_[nt][j0 + 1] *= corr;
                }
            }

            // ---- O += P V  (P: C-layout -> A-layout via quad shuffles) ----
            const int srcA = (lane & ~3) | (tig >> 1);
            const int srcB = srcA + 2;
            const bool odd = (tig & 1);
            #pragma unroll
            for (int kk2 = 0; kk2 < 8; kk2++) {
                uint32_t pa[4];
                {
                    float x0 = __shfl_sync(0xffffffffu, S_[kk2][0], srcA);
                    float x1 = __shfl_sync(0xffffffffu, S_[kk2][1], srcA);
                    float x2 = __shfl_sync(0xffffffffu, S_[kk2][2], srcA);
                    float x3 = __shfl_sync(0xffffffffu, S_[kk2][3], srcA);
                    float y0 = __shfl_sync(0xffffffffu, S_[kk2][0], srcB);
                    float y1 = __shfl_sync(0xffffffffu, S_[kk2][1], srcB);
                    float y2 = __shfl_sync(0xffffffffu, S_[kk2][2], srcB);
                    float y3 = __shfl_sync(0xffffffffu, S_[kk2][3], srcB);
                    pa[0] = fbits(odd ? x1 : x0);
                    pa[1] = fbits(odd ? x3 : x2);
                    pa[2] = fbits(odd ? y1 : y0);
                    pa[3] = fbits(odd ? y3 : y2);
                }
                const float* vr0 = sV + (kk2 * 8 + tig) * RS;
                const float* vr1 = vr0 + 4 * RS;
                #pragma unroll
                for (int nt = 0; nt < 8; nt++) {
                    int dvo = VOFF(8 * nt) + g;   // compile-time 8*nt part
                    uint32_t b0 = fbits(vr0[dvo]);
                    uint32_t b1 = fbits(vr1[dvo]);
                    mma8(O_[nt], pa, b0, b1);
                }
            }
        }

        __syncthreads();   // next tile's K/V visible; buffers swap
    }

    // ---- epilogue ----
    #pragma unroll
    for (int rh = 0; rh < 2; rh++) {
        float inv = 1.f / l_[rh];
        int tq  = qt * 128 + 16 * w + g + rh * 8;
        int pos = seg + offs + tq * rate;
        float* go = O + ((size_t)pos * 8 + head) * 64;
        int j0 = rh * 2;
        #pragma unroll
        for (int nt = 0; nt < 8; nt++) {
            float2 wv = make_float2(O_[nt][j0] * inv, O_[nt][j0 + 1] * inv);
            *reinterpret_cast<float2*>(&go[nt * 8 + 2 * tig]) = wv;
        }
    }
}

extern "C" void kernel_launch(void* const* d_in, const int* in_sizes, int n_in,
                              void* d_out, int out_size) {
    const float* q = (const float*)d_in[0];
    const float* k = (const float*)d_in[1];
    const float* v = (const float*)d_in[2];
    float* out = (float*)d_out;

    static bool attr_set = false;
    if (!attr_set) {
        cudaFuncSetAttribute(dilated_attn_mma_kernel,
                             cudaFuncAttributeMaxDynamicSharedMemorySize, SMEM_BYTES);
        attr_set = true;
    }

    zero_even_kernel<<<1024, 256>>>(out);
    dilated_attn_mma_kernel<<<384, 256, SMEM_BYTES>>>(q, k, v, out);
}